// round 10
// baseline (speedup 1.0000x reference)
#include <cuda_runtime.h>

// SmallRNN: h_t = tanh(x_t * w_ih^T + b_ih + h_{t-1} * w_hh^T + b_hh), out = h_T @ fc_w^T + fc_b
// Shapes: x [B=4096, T=2048, I=1], w_ih [8,1], w_hh [8,8], b_* [8], fc_w [1,8], fc_b [1]
//
// R8: 8 lanes per hidden-vector; each lane carries TWO independent batch
// elements (interleaved recurrences). 512 warps -> 128 blocks x 128 thr ->
// 1 block/SM, 1 warp/SMSP: no cross-warp arbitration; the sibling chain's
// instructions fill each chain's stall slots. Exchange via smem
// (asm STS -> 2x LDS.128 with memory clobbers, proven in R6). tanh.approx
// for the first T-64 steps, exact ex2+rcp tail (recurrence contracts).

#define TBLOCK 128
#define EXACT_TAIL 64

__device__ __forceinline__ float ex2f(float x) {
    float y; asm("ex2.approx.f32 %0, %1;" : "=f"(y) : "f"(x)); return y;
}
__device__ __forceinline__ float rcpf(float x) {
    float y; asm("rcp.approx.f32 %0, %1;" : "=f"(y) : "f"(x)); return y;
}
__device__ __forceinline__ float tanhf_approx(float x) {
    float y; asm("tanh.approx.f32 %0, %1;" : "=f"(y) : "f"(x)); return y;
}

template <bool EXACT>
__device__ __forceinline__ float act(float s) {
    if (EXACT) {
        const float c2 = 2.8853900817779268f; // 2*log2(e)
        float e = ex2f(c2 * s);
        float r = rcpf(e + 1.0f);
        return fmaf(-2.0f, r, 1.0f); // tanh(s) = 1 - 2*sigmoid(-2s)
    } else {
        return tanhf_approx(s);
    }
}

template <bool EXACT>
__device__ __forceinline__ void rnn_step2(float& hA, float& hB, float xvA, float xvB,
                                          unsigned ownA, unsigned ownB,
                                          unsigned vecA, unsigned vecB,
                                          const float w[8], float Bj, float wih) {
    asm volatile("st.shared.f32 [%0], %1;" :: "r"(ownA), "f"(hA) : "memory");
    asm volatile("st.shared.f32 [%0], %1;" :: "r"(ownB), "f"(hB) : "memory");
    float p0, p1, p2, p3, p4, p5, p6, p7;
    float q0, q1, q2, q3, q4, q5, q6, q7;
    asm volatile("ld.shared.v4.f32 {%0,%1,%2,%3}, [%4];"
                 : "=f"(p0), "=f"(p1), "=f"(p2), "=f"(p3) : "r"(vecA) : "memory");
    asm volatile("ld.shared.v4.f32 {%0,%1,%2,%3}, [%4];"
                 : "=f"(p4), "=f"(p5), "=f"(p6), "=f"(p7) : "r"(vecA + 16u) : "memory");
    asm volatile("ld.shared.v4.f32 {%0,%1,%2,%3}, [%4];"
                 : "=f"(q0), "=f"(q1), "=f"(q2), "=f"(q3) : "r"(vecB) : "memory");
    asm volatile("ld.shared.v4.f32 {%0,%1,%2,%3}, [%4];"
                 : "=f"(q4), "=f"(q5), "=f"(q6), "=f"(q7) : "r"(vecB + 16u) : "memory");
    // chain A tree
    float aA = fmaf(xvA, wih, Bj);
    aA = fmaf(p0, w[0], aA);
    float bA = p1 * w[1];
    float cA = p2 * w[2];
    float dA = p3 * w[3];
    aA = fmaf(p4, w[4], aA);
    bA = fmaf(p5, w[5], bA);
    cA = fmaf(p6, w[6], cA);
    dA = fmaf(p7, w[7], dA);
    float sA = (aA + bA) + (cA + dA);
    // chain B tree
    float aB = fmaf(xvB, wih, Bj);
    aB = fmaf(q0, w[0], aB);
    float bB = q1 * w[1];
    float cB = q2 * w[2];
    float dB = q3 * w[3];
    aB = fmaf(q4, w[4], aB);
    bB = fmaf(q5, w[5], bB);
    cB = fmaf(q6, w[6], cB);
    dB = fmaf(q7, w[7], dB);
    float sB = (aB + bB) + (cB + dB);
    hA = act<EXACT>(sA);
    hB = act<EXACT>(sB);
}

__global__ void __launch_bounds__(TBLOCK)
SmallRNN_kernel(const float* __restrict__ x,
                const float* __restrict__ w_ih,
                const float* __restrict__ w_hh,
                const float* __restrict__ b_ih,
                const float* __restrict__ b_hh,
                const float* __restrict__ fc_w,
                const float* __restrict__ fc_b,
                float* __restrict__ out,
                int B, int T) {
    __shared__ float sh[2 * TBLOCK];

    int tx = threadIdx.x;          // 0..127; group g = tx>>3, lane j = tx&7
    int j = tx & 7;
    int g = tx >> 3;               // 16 groups per block

    // Each block handles 32 elements: A = blk*32 + g, B = blk*32 + 16 + g
    int eA_raw = blockIdx.x * 32 + g;
    int eB_raw = eA_raw + 16;
    int eA = (eA_raw < B) ? eA_raw : (B - 1);
    int eB = (eB_raw < B) ? eB_raw : (B - 1);

    unsigned base = (unsigned)__cvta_generic_to_shared(sh);
    unsigned ownA = base + (unsigned)tx * 4u;            // A region [0..127]
    unsigned vecA = base + (unsigned)(tx & ~7) * 4u;
    unsigned ownB = ownA + (unsigned)TBLOCK * 4u;        // B region [128..255]
    unsigned vecB = vecA + (unsigned)TBLOCK * 4u;

    float w[8];
#pragma unroll
    for (int k = 0; k < 8; k++) w[k] = w_hh[j * 8 + k];
    float Bj  = b_ih[j] + b_hh[j];
    float wih = w_ih[j];

    const float* xpA = x + (size_t)eA * (size_t)T;
    const float* xpB = x + (size_t)eB * (size_t)T;
    float hA = 0.0f, hB = 0.0f;

    int Tmain = T - EXACT_TAIL;
    if (Tmain < 0) Tmain = 0;
    int Tm = Tmain & ~7;

    bool aligned = (((unsigned long long)xpA & 15ull) == 0ull) &&
                   (((unsigned long long)xpB & 15ull) == 0ull);
    if (aligned && Tm > 0) {
        float4 aA0 = *(const float4*)(xpA);
        float4 aA1 = *(const float4*)(xpA + 4);
        float4 aB0 = *(const float4*)(xpB);
        float4 aB1 = *(const float4*)(xpB + 4);
        for (int t = 0; t < Tm; t += 8) {
            float4 nA0, nA1, nB0, nB1;
            if (t + 8 < Tm) {
                nA0 = *(const float4*)(xpA + t + 8);
                nA1 = *(const float4*)(xpA + t + 12);
                nB0 = *(const float4*)(xpB + t + 8);
                nB1 = *(const float4*)(xpB + t + 12);
            } else {
                nA0 = make_float4(0.f, 0.f, 0.f, 0.f);
                nA1 = nA0; nB0 = nA0; nB1 = nA0;
            }
            rnn_step2<false>(hA, hB, aA0.x, aB0.x, ownA, ownB, vecA, vecB, w, Bj, wih);
            rnn_step2<false>(hA, hB, aA0.y, aB0.y, ownA, ownB, vecA, vecB, w, Bj, wih);
            rnn_step2<false>(hA, hB, aA0.z, aB0.z, ownA, ownB, vecA, vecB, w, Bj, wih);
            rnn_step2<false>(hA, hB, aA0.w, aB0.w, ownA, ownB, vecA, vecB, w, Bj, wih);
            rnn_step2<false>(hA, hB, aA1.x, aB1.x, ownA, ownB, vecA, vecB, w, Bj, wih);
            rnn_step2<false>(hA, hB, aA1.y, aB1.y, ownA, ownB, vecA, vecB, w, Bj, wih);
            rnn_step2<false>(hA, hB, aA1.z, aB1.z, ownA, ownB, vecA, vecB, w, Bj, wih);
            rnn_step2<false>(hA, hB, aA1.w, aB1.w, ownA, ownB, vecA, vecB, w, Bj, wih);
            aA0 = nA0; aA1 = nA1; aB0 = nB0; aB1 = nB1;
        }
    } else {
        Tm = 0;
    }
    for (int t = Tm; t < Tmain; t++) {
        rnn_step2<false>(hA, hB, xpA[t], xpB[t], ownA, ownB, vecA, vecB, w, Bj, wih);
    }
    for (int t = Tmain; t < T; t++) {
        rnn_step2<true>(hA, hB, xpA[t], xpB[t], ownA, ownB, vecA, vecB, w, Bj, wih);
    }

    // FC for both elements: out[e] = sum_j h_j * fc_w[j] + fc_b
    float fw = fc_w[j];
    float vA = hA * fw;
    float vB = hB * fw;
    vA += __shfl_xor_sync(0xffffffffu, vA, 4, 8);
    vA += __shfl_xor_sync(0xffffffffu, vA, 2, 8);
    vA += __shfl_xor_sync(0xffffffffu, vA, 1, 8);
    vB += __shfl_xor_sync(0xffffffffu, vB, 4, 8);
    vB += __shfl_xor_sync(0xffffffffu, vB, 2, 8);
    vB += __shfl_xor_sync(0xffffffffu, vB, 1, 8);
    if (j == 0) {
        float fb = fc_b[0];
        if (eA_raw < B) out[eA] = vA + fb;
        if (eB_raw < B) out[eB] = vB + fb;
    }
}

extern "C" void kernel_launch(void* const* d_in, const int* in_sizes, int n_in,
                              void* d_out, int out_size) {
    const float* x    = (const float*)d_in[0];
    const float* w_ih = (const float*)d_in[1];
    const float* w_hh = (const float*)d_in[2];
    const float* b_ih = (const float*)d_in[3];
    const float* b_hh = (const float*)d_in[4];
    const float* fc_w = (const float*)d_in[5];
    const float* fc_b = (const float*)d_in[6];
    float* out = (float*)d_out;

    int B = out_size;                 // O = 1
    int T = in_sizes[0] / B;          // I = 1
    // 32 elements per block (16 groups x 2 elements/lane)
    int grid = (B + 31) / 32;
    SmallRNN_kernel<<<grid, TBLOCK>>>(x, w_ih, w_hh, b_ih, b_hh, fc_w, fc_b,
                                      out, B, T);
}

// round 11
// speedup vs baseline: 1.1891x; 1.1891x over previous
#include <cuda_runtime.h>

// SmallRNN: h_t = tanh(x_t * w_ih^T + b_ih + h_{t-1} * w_hh^T + b_hh), out = h_T @ fc_w^T + fc_b
// Shapes: x [B=4096, T=2048, I=1], w_ih [8,1], w_hh [8,8], b_* [8], fc_w [1,8], fc_b [1]
//
// R9: ONE thread per batch element. No cross-lane dependency -> no exchange on
// the chain at all. Each thread carries h[8] and computes all 8 dot products
// with packed f32x2 FMAs (fma.rn.f32x2): 36 FFMA2 + 8 MUFU per step.
// Throughput-bound at the FMA-pipe floor (~72 cyc/warp-step for 32 elements),
// below the ~85-cyc smem-exchange chain floor of the 8-lane design.
// tanh.approx for first T-64 steps; exact ex2+rcp tail (recurrence contracts).

#define EXACT_TAIL 64
typedef unsigned long long u64;

#define FMA2(d, a, b, c) \
    asm("fma.rn.f32x2 %0, %1, %2, %3;" : "=l"(d) : "l"(a), "l"(b), "l"(c))
#define PACK2(d, lo, hi) \
    asm("mov.b64 %0, {%1, %2};" : "=l"(d) : "f"(lo), "f"(hi))
#define UNPACK2(lo, hi, s) \
    asm("mov.b64 {%0, %1}, %2;" : "=f"(lo), "=f"(hi) : "l"(s))

__device__ __forceinline__ float ex2f(float x) {
    float y; asm("ex2.approx.f32 %0, %1;" : "=f"(y) : "f"(x)); return y;
}
__device__ __forceinline__ float rcpf(float x) {
    float y; asm("rcp.approx.f32 %0, %1;" : "=f"(y) : "f"(x)); return y;
}
__device__ __forceinline__ float tanhf_approx(float x) {
    float y; asm("tanh.approx.f32 %0, %1;" : "=f"(y) : "f"(x)); return y;
}

struct Packed {
    u64 W[4][8];   // W[p][k] = pack(w_hh[2p][k], w_hh[2p+1][k])
    u64 WIH[4];    // pack(w_ih[2p], w_ih[2p+1])
    u64 BP[4];     // pack(bias[2p], bias[2p+1])
};

template <bool EXACT>
__device__ __forceinline__ void rnn_step(float h[8], float xv, const Packed& P) {
    u64 xx; PACK2(xx, xv, xv);
    u64 hb[8];
#pragma unroll
    for (int k = 0; k < 8; k++) PACK2(hb[k], h[k], h[k]);
    u64 u[4];
#pragma unroll
    for (int p = 0; p < 4; p++) FMA2(u[p], xx, P.WIH[p], P.BP[p]);
    // 4 independent accumulation chains (depth 8 each) keep the FMA pipe fed
#pragma unroll
    for (int k = 0; k < 8; k++) {
#pragma unroll
        for (int p = 0; p < 4; p++) FMA2(u[p], hb[k], P.W[p][k], u[p]);
    }
    float s[8];
#pragma unroll
    for (int p = 0; p < 4; p++) UNPACK2(s[2 * p], s[2 * p + 1], u[p]);
#pragma unroll
    for (int j = 0; j < 8; j++) {
        if (EXACT) {
            const float c2 = 2.8853900817779268f; // 2*log2(e)
            float e = ex2f(c2 * s[j]);
            float r = rcpf(e + 1.0f);
            h[j] = fmaf(-2.0f, r, 1.0f);          // tanh = 1 - 2*sigmoid(-2s)
        } else {
            h[j] = tanhf_approx(s[j]);
        }
    }
}

__global__ void __launch_bounds__(32)
SmallRNN_kernel(const float* __restrict__ x,
                const float* __restrict__ w_ih,
                const float* __restrict__ w_hh,
                const float* __restrict__ b_ih,
                const float* __restrict__ b_hh,
                const float* __restrict__ fc_w,
                const float* __restrict__ fc_b,
                float* __restrict__ out,
                int B, int T) {
    int e = blockIdx.x * 32 + threadIdx.x;   // one element per thread
    if (e >= B) return;                      // no warp-collective ops: safe

    Packed P;
#pragma unroll
    for (int p = 0; p < 4; p++) {
#pragma unroll
        for (int k = 0; k < 8; k++) {
            PACK2(P.W[p][k], w_hh[(2 * p) * 8 + k], w_hh[(2 * p + 1) * 8 + k]);
        }
        PACK2(P.WIH[p], w_ih[2 * p], w_ih[2 * p + 1]);
        float blo = b_ih[2 * p] + b_hh[2 * p];
        float bhi = b_ih[2 * p + 1] + b_hh[2 * p + 1];
        PACK2(P.BP[p], blo, bhi);
    }

    const float* xp = x + (size_t)e * (size_t)T;
    float h[8];
#pragma unroll
    for (int j = 0; j < 8; j++) h[j] = 0.0f;

    int Tmain = T - EXACT_TAIL;
    if (Tmain < 0) Tmain = 0;
    int Tm = Tmain & ~7;

    if (((unsigned long long)xp & 15ull) == 0ull && Tm > 0) {
        float4 xa = *(const float4*)(xp);
        float4 xb_ = *(const float4*)(xp + 4);
        for (int t = 0; t < Tm; t += 8) {
            float4 xn0, xn1;
            if (t + 8 < Tm) {
                xn0 = *(const float4*)(xp + t + 8);
                xn1 = *(const float4*)(xp + t + 12);
            } else {
                xn0 = make_float4(0.f, 0.f, 0.f, 0.f);
                xn1 = xn0;
            }
            rnn_step<false>(h, xa.x,  P);
            rnn_step<false>(h, xa.y,  P);
            rnn_step<false>(h, xa.z,  P);
            rnn_step<false>(h, xa.w,  P);
            rnn_step<false>(h, xb_.x, P);
            rnn_step<false>(h, xb_.y, P);
            rnn_step<false>(h, xb_.z, P);
            rnn_step<false>(h, xb_.w, P);
            xa = xn0;
            xb_ = xn1;
        }
    } else {
        Tm = 0;
    }
    for (int t = Tm; t < Tmain; t++) rnn_step<false>(h, xp[t], P);
    for (int t = Tmain; t < T; t++)  rnn_step<true>(h, xp[t], P);

    // out[e] = sum_j h_j * fc_w[j] + fc_b
    float v = fc_b[0];
#pragma unroll
    for (int j = 0; j < 8; j++) v = fmaf(h[j], fc_w[j], v);
    out[e] = v;
}

extern "C" void kernel_launch(void* const* d_in, const int* in_sizes, int n_in,
                              void* d_out, int out_size) {
    const float* x    = (const float*)d_in[0];
    const float* w_ih = (const float*)d_in[1];
    const float* w_hh = (const float*)d_in[2];
    const float* b_ih = (const float*)d_in[3];
    const float* b_hh = (const float*)d_in[4];
    const float* fc_w = (const float*)d_in[5];
    const float* fc_b = (const float*)d_in[6];
    float* out = (float*)d_out;

    int B = out_size;                 // O = 1
    int T = in_sizes[0] / B;          // I = 1
    int grid = (B + 31) / 32;         // 1 warp per block -> max SM spread
    SmallRNN_kernel<<<grid, 32>>>(x, w_ih, w_hh, b_ih, b_hh, fc_w, fc_b,
                                  out, B, T);
}